// round 10
// baseline (speedup 1.0000x reference)
#include <cuda_runtime.h>
#include <cstdint>
#include <math.h>

#define BATCH   32
#define TT      32
#define DIN     128
#define CSZ     4
#define SL      128
#define CTRLD   256
#define NHEADS  5
#define NT      512
#define MEMP    65

// ---- SMEM layout (float offsets) ----
#define OFF_MEM    0        // 8320
#define OFF_PX     8320     // 1920 : instr partials [cta][480]; rp2 (a,u) overlay
#define OFF_EXG    10240    // 650
#define OFF_HALO   10890    // 20 : L{ex,wp}x5, R{ex,wp}x5
#define OFF_STATS  10910    // 20
#define OFF_SSUM   10930    // 20
#define OFF_REDB   10950    // 80
#define OFF_KRED   11030    // 10
#define OFF_HP     11040    // 40
#define OFF_PINV   11080    // 8
#define OFF_RWA    11088    // 512
#define OFF_RWB    11600    // 512
#define OFF_WWA    12112    // 128
#define OFF_WWB    12240    // 128
#define OFF_RVEC   12368    // 256
#define OFF_H64    12624    // 64
#define OFF_KV     12688    // 320
#define OFF_EV     13008    // 64
#define OFF_AV     13072    // 64
#define OFF_HBS    13136    // 480
#define OFF_BUF    13616    // 2048 : GH a (1024) + u (1024)
#define OFF_XP     15664    // 2048 : XP[t][64] = x_t @ Wc_x + bc
#define OFF_SWC    17712    // 8192 : mm1 r-rows 0..127 cache
#define OFF_SHK    25904    // 30720 : mm2 full cache, k-major stride 480
#define SMEM_FLOATS 56624   // 226496 bytes

__device__ __forceinline__ float sigmoidf_(float v) { return 1.f / (1.f + __expf(-v)); }
__device__ __forceinline__ float softplusf_(float v) { return v > 20.f ? v : log1pf(__expf(v)); }

__device__ __forceinline__ uint32_t smem_u32(const void* p) {
    uint32_t a;
    asm("{ .reg .u64 t; cvta.to.shared.u64 t, %1; cvt.u32.u64 %0, t; }" : "=r"(a) : "l"(p));
    return a;
}
__device__ __forceinline__ uint32_t mapa_u32(uint32_t a, uint32_t rank) {
    uint32_t r;
    asm("mapa.shared::cluster.u32 %0, %1, %2;" : "=r"(r) : "r"(a), "r"(rank));
    return r;
}
__device__ __forceinline__ void st_remote(uint32_t a, float v) {
    asm volatile("st.shared::cluster.f32 [%0], %1;" :: "r"(a), "f"(v) : "memory");
}
__device__ __forceinline__ void st_remote64(uint32_t a, unsigned long long v) {
    asm volatile("st.shared::cluster.u64 [%0], %1;" :: "r"(a), "l"(v) : "memory");
}
__device__ __forceinline__ uint32_t ctarank() {
    uint32_t r; asm("mov.u32 %0, %%cluster_ctarank;" : "=r"(r)); return r;
}
#define CLUSTER_ARRIVE() asm volatile("barrier.cluster.arrive.aligned;" ::: "memory")
#define CLUSTER_WAIT()   asm volatile("barrier.cluster.wait.aligned;" ::: "memory")
#define CLUSTER_SYNC() do { CLUSTER_ARRIVE(); CLUSTER_WAIT(); } while (0)

__device__ __forceinline__ unsigned long long pack2(float a, float b) {
    return (unsigned long long)__float_as_uint(a) |
           ((unsigned long long)__float_as_uint(b) << 32);
}

__global__ __launch_bounds__(NT, 1) __cluster_dims__(CSZ, 1, 1)
void ntm_kernel(const float* __restrict__ x, const float* __restrict__ Wc,
                const float* __restrict__ bc, const float* __restrict__ hk,
                const float* __restrict__ hb, float* __restrict__ out)
{
    extern __shared__ float sm[];
    float* Mem   = sm + OFF_MEM;
    float* px    = sm + OFF_PX;
    float* exg   = sm + OFF_EXG;
    float* halo  = sm + OFF_HALO;
    float* stats = sm + OFF_STATS;
    float* ssum  = sm + OFF_SSUM;
    float* redb  = sm + OFF_REDB;
    float* kred  = sm + OFF_KRED;
    float* hp    = sm + OFF_HP;
    float* pinv  = sm + OFF_PINV;
    float* rvec  = sm + OFF_RVEC;
    float* h64   = sm + OFF_H64;
    float* kvec  = sm + OFF_KV;
    float4* KV4  = reinterpret_cast<float4*>(kvec);
    float* evec  = sm + OFF_EV;
    float* avec  = sm + OFF_AV;
    float* hbs   = sm + OFF_HBS;
    float* buf   = sm + OFF_BUF;
    float* XP    = sm + OFF_XP;
    float4* XP4  = reinterpret_cast<float4*>(XP);
    float4* SWC4 = reinterpret_cast<float4*>(sm + OFF_SWC);
    float* SHK   = sm + OFF_SHK;
    unsigned long long* rp2 = reinterpret_cast<unsigned long long*>(sm + OFF_PX);

    const int tid  = threadIdx.x;
    const int wrp  = tid >> 5;
    const int lane = tid & 31;
    const int b    = blockIdx.x >> 2;
    const uint32_t r = ctarank();
    const uint32_t left  = (r + 3) & 3;
    const uint32_t right = (r + 1) & 3;

    const uint32_t sbase = smem_u32(sm);
    uint32_t pb[CSZ];
#pragma unroll
    for (int c = 0; c < CSZ; ++c) pb[c] = mapa_u32(sbase, c);

    // ---- init state ----
    for (int i = tid; i < SL * MEMP; i += NT) Mem[i] = 0.f;
    for (int i = tid; i < 512; i += NT) (sm + OFF_RWA)[i] = 0.f;
    if (tid < SL)  (sm + OFF_WWA)[tid] = 0.f;
    if (tid < 256) rvec[tid] = 0.f;
    if (tid < 8)   pinv[tid] = 1.f;
    if (tid < 20)  halo[tid] = 0.f;
    if (tid < 478) hbs[tid] = hb[tid];
    {
        const float4* W4 = reinterpret_cast<const float4*>(Wc);
        for (int i = tid; i < 16 * 128; i += NT) {
            int w = i >> 7, k = i & 127;
            SWC4[i] = W4[(128 + k) * 64 + (int)r * 16 + w];
        }
        for (int kk = 0; kk < 64; ++kk)
            if (tid < 478)
                SHK[kk * 480 + tid] = hk[((int)r * 64 + kk) * 478 + tid];
        {
            const int tt = tid >> 4, cg = tid & 15;
            const float* xr = x + (b * TT + tt) * DIN;
            float4 acc = make_float4(0.f, 0.f, 0.f, 0.f);
            const float4* Wx = W4 + (int)r * 16 + cg;
#pragma unroll 8
            for (int k = 0; k < 128; ++k) {
                float xv = xr[k];
                float4 w = Wx[k * 64];
                acc.x = fmaf(xv, w.x, acc.x); acc.y = fmaf(xv, w.y, acc.y);
                acc.z = fmaf(xv, w.z, acc.z); acc.w = fmaf(xv, w.w, acc.w);
            }
            float4 b4 = reinterpret_cast<const float4*>(bc)[(int)r * 16 + cg];
            acc.x += b4.x; acc.y += b4.y; acc.z += b4.z; acc.w += b4.w;
            XP4[tt * 16 + cg] = acc;
        }
    }
    __syncthreads();
    CLUSTER_SYNC();

    for (int t = 0; t < TT; ++t) {
        const int par = t & 1;
        float* RWrd = sm + (par ? OFF_RWB : OFF_RWA);
        float* RWwr = sm + (par ? OFF_RWA : OFF_RWB);
        float4* RW4rd = reinterpret_cast<float4*>(RWrd);
        float4* RW4wr = reinterpret_cast<float4*>(RWwr);
        float* wwrd = sm + (par ? OFF_WWB : OFF_WWA);
        float* wwwr = sm + (par ? OFF_WWA : OFF_WWB);

        // ---- B: mm1 r-part only (XP holds x-part + bias) ----
        {
            float a0 = 0.f, a1 = 0.f, a2 = 0.f, a3 = 0.f;
            const float4* cw = SWC4 + wrp * 128;
#pragma unroll
            for (int i = 0; i < 4; ++i) {               // cached k=0..127
                int k = lane + 32 * i;
                float c = rvec[k];
                float4 w = cw[k];
                a0 = fmaf(c, w.x, a0); a1 = fmaf(c, w.y, a1);
                a2 = fmaf(c, w.z, a2); a3 = fmaf(c, w.w, a3);
            }
            const float4* W4s = reinterpret_cast<const float4*>(Wc)
                                + 256 * 64 + (int)r * 16 + wrp;
#pragma unroll
            for (int i = 0; i < 4; ++i) {               // streamed k=128..255
                int k = lane + 32 * i;
                float c = rvec[128 + k];
                float4 w = W4s[k * 64];
                a0 = fmaf(c, w.x, a0); a1 = fmaf(c, w.y, a1);
                a2 = fmaf(c, w.z, a2); a3 = fmaf(c, w.w, a3);
            }
#pragma unroll
            for (int o = 16; o > 0; o >>= 1) {
                a0 += __shfl_xor_sync(0xffffffffu, a0, o);
                a1 += __shfl_xor_sync(0xffffffffu, a1, o);
                a2 += __shfl_xor_sync(0xffffffffu, a2, o);
                a3 += __shfl_xor_sync(0xffffffffu, a3, o);
            }
            if (lane < 4) {
                float av = (lane == 0) ? a0 : (lane == 1) ? a1 : (lane == 2) ? a2 : a3;
                float hv = tanhf(av + XP[t * 64 + 4 * wrp + lane]);
                h64[4 * wrp + lane] = hv;
                if (t == TT - 1) out[b * CTRLD + (int)r * 64 + 4 * wrp + lane] = hv;
            }
        }
        __syncthreads();  // S1

        // ---- C: mm2 single pass, full SMEM ----
        if (wrp < 15) {
            float v = 0.f;
#pragma unroll 16
            for (int k = 0; k < 64; ++k)
                v = fmaf(h64[k], SHK[k * 480 + tid], v);
            if (tid < 478) px[r * 480 + tid] = v;
            float vo = __shfl_down_sync(0xffffffffu, v, 1);
            if (!(tid & 1) && tid < 477) {
                unsigned long long pk = pack2(v, vo);
#pragma unroll
                for (int c = 0; c < CSZ; ++c)
                    if (c != (int)r)
                        st_remote64(pb[c] + (OFF_PX + (int)r * 480 + tid) * 4, pk);
            }
        }
        CLUSTER_ARRIVE();  // CS2 arrive

        // ---- CS2 gap: Mem norms ----
        const int s  = tid >> 2;
        const int pq = tid & 3;
        float mn_reg;
        {
            float nn = 0.f;
            const float* mr = Mem + s * MEMP + pq * 16;
#pragma unroll
            for (int j = 0; j < 16; ++j) nn = fmaf(mr[j], mr[j], nn);
            nn += __shfl_xor_sync(0xffffffffu, nn, 1);
            nn += __shfl_xor_sync(0xffffffffu, nn, 2);
            mn_reg = sqrtf(nn);
        }
        CLUSTER_WAIT();    // CS2 wait

        // ---- D: parse (fold partials) ----
        if (tid < 320) {
            int h = tid >> 6, m = tid & 63;
            int idx = (h < 4 ? h * 70 : 280) + m;
            float v = px[idx] + px[480 + idx] + px[960 + idx] + px[1440 + idx] + hbs[idx];
            kvec[tid] = v;
            float sq = v * v;
#pragma unroll
            for (int o = 16; o > 0; o >>= 1) sq += __shfl_xor_sync(0xffffffffu, sq, o);
            if (lane == 0) kred[wrp] = sq;
        } else if (tid < 384) {
            int idx = 350 + (tid - 320);
            evec[tid - 320] = px[idx] + px[480 + idx] + px[960 + idx] + px[1440 + idx] + hbs[idx];
        } else if (tid < 448) {
            int idx = 414 + (tid - 384);
            avec[tid - 384] = px[idx] + px[480 + idx] + px[960 + idx] + px[1440 + idx] + hbs[idx];
        } else if (tid < 448 + NHEADS) {
            int h = tid - 448;
            int bidx = (h < 4 ? h * 70 : 280);
            float sv[6];
#pragma unroll
            for (int j = 0; j < 6; ++j) {
                int idx = bidx + 64 + j;
                sv[j] = px[idx] + px[480 + idx] + px[960 + idx] + px[1440 + idx] + hbs[idx];
            }
            hp[h * 8 + 0] = __expf(sv[0]);
            hp[h * 8 + 1] = sigmoidf_(sv[1]);
            float s0 = sv[2], s1 = sv[3], s2 = sv[4];
            float mx = fmaxf(s0, fmaxf(s1, s2));
            float e0 = __expf(s0 - mx), e1 = __expf(s1 - mx), e2 = __expf(s2 - mx);
            float inv = 1.f / (e0 + e1 + e2);
            hp[h * 8 + 3] = e0 * inv; hp[h * 8 + 4] = e1 * inv; hp[h * 8 + 5] = e2 * inv;
            hp[h * 8 + 2] = softplusf_(sv[5]) + 1.f;
        }
        __syncthreads();  // S3

        // ---- E: sim + exp ----
        float ex[NHEADS];
        {
            float d[NHEADS] = {0.f, 0.f, 0.f, 0.f, 0.f};
            const float* mr = Mem + s * MEMP + pq * 16;
#pragma unroll
            for (int j = 0; j < 4; ++j) {
                float m0 = mr[4 * j], m1 = mr[4 * j + 1], m2 = mr[4 * j + 2], m3 = mr[4 * j + 3];
#pragma unroll
                for (int h = 0; h < NHEADS; ++h) {
                    float4 kq = KV4[h * 16 + pq * 4 + j];
                    d[h] = fmaf(m0, kq.x, d[h]); d[h] = fmaf(m1, kq.y, d[h]);
                    d[h] = fmaf(m2, kq.z, d[h]); d[h] = fmaf(m3, kq.w, d[h]);
                }
            }
#pragma unroll
            for (int o = 1; o <= 2; o <<= 1)
#pragma unroll
                for (int h = 0; h < NHEADS; ++h) d[h] += __shfl_xor_sync(0xffffffffu, d[h], o);
#pragma unroll
            for (int h = 0; h < NHEADS; ++h) {
                float kn = sqrtf(kred[2 * h] + kred[2 * h + 1]);
                float z = hp[h * 8 + 0] * (d[h] / (kn * mn_reg + 1e-8f));
                ex[h] = __expf(z);
            }
        }
        if (pq == 0) {
#pragma unroll
            for (int h = 0; h < NHEADS; ++h) exg[h * 130 + s + 1] = ex[h];
        }
        if (tid == 0) {
            float4 wp4 = RW4rd[0];
            float wpv[5] = {wp4.x * pinv[0], wp4.y * pinv[1], wp4.z * pinv[2],
                            wp4.w * pinv[3], wwrd[0] * pinv[4]};
#pragma unroll
            for (int h = 0; h < NHEADS; ++h)
                st_remote64(pb[left] + (OFF_HALO + 10 + h * 2) * 4, pack2(ex[h], wpv[h]));
        }
        if (tid == (SL - 1) * 4) {
            float4 wp4 = RW4rd[SL - 1];
            float wpv[5] = {wp4.x * pinv[0], wp4.y * pinv[1], wp4.z * pinv[2],
                            wp4.w * pinv[3], wwrd[SL - 1] * pinv[4]};
#pragma unroll
            for (int h = 0; h < NHEADS; ++h)
                st_remote64(pb[right] + (OFF_HALO + h * 2) * 4, pack2(ex[h], wpv[h]));
        }
        {
            float tmp[NHEADS];
#pragma unroll
            for (int h = 0; h < NHEADS; ++h) tmp[h] = (pq == 0) ? ex[h] : 0.f;
#pragma unroll
            for (int o = 16; o > 0; o >>= 1)
#pragma unroll
                for (int h = 0; h < NHEADS; ++h)
                    tmp[h] += __shfl_xor_sync(0xffffffffu, tmp[h], o);
            if (lane == 0)
#pragma unroll
                for (int h = 0; h < NHEADS; ++h) redb[wrp * 5 + h] = tmp[h];
        }
        __syncthreads();  // S4
        if (tid < NHEADS) {
            float acc = 0.f;
#pragma unroll
            for (int w = 0; w < 16; ++w) acc += redb[w * 5 + tid];
            stats[r * 5 + tid] = acc;
#pragma unroll
            for (int c = 0; c < CSZ; ++c)
                if (c != (int)r) st_remote(pb[c] + (OFF_STATS + (int)r * 5 + tid) * 4, acc);
        }
        CLUSTER_ARRIVE();  // CS3 arrive

        // ---- CS3 gap: linearized wsh precompute  (wsh = A*invgs + B) ----
        float A[NHEADS], B[NHEADS];
        if (tid < SL) {
            float4 c4 = RW4rd[tid];
            float wpc[5] = {c4.x, c4.y, c4.z, c4.w, wwrd[tid]};
            int im = (tid > 0) ? tid - 1 : 0;
            int ip = (tid < SL - 1) ? tid + 1 : SL - 1;
            float4 m4 = RW4rd[im];
            float wpm[5] = {m4.x, m4.y, m4.z, m4.w, wwrd[im]};
            float4 p4 = RW4rd[ip];
            float wpp[5] = {p4.x, p4.y, p4.z, p4.w, wwrd[ip]};
#pragma unroll
            for (int h = 0; h < NHEADS; ++h) {
                float g  = hp[h * 8 + 1];
                float s3 = hp[h * 8 + 3], s4v = hp[h * 8 + 4], s5 = hp[h * 8 + 5];
                float pv = pinv[h];
                float exc  = exg[h * 130 + tid + 1];
                float exm  = (tid > 0)      ? exg[h * 130 + tid]     : 0.f;
                float exp_ = (tid < SL - 1) ? exg[h * 130 + tid + 2] : 0.f;
                A[h] = g * (s3 * exp_ + s4v * exc + s5 * exm);
                float bm = (tid > 0)      ? wpm[h] * pv : 0.f;
                float bp = (tid < SL - 1) ? wpp[h] * pv : 0.f;
                B[h] = (1.f - g) * (s3 * bp + s4v * wpc[h] * pv + s5 * bm);
            }
        }
        CLUSTER_WAIT();    // CS3 wait

        // ---- F: finish shift + sharpen ----
        if (tid < SL) {
            float invgs[NHEADS], wt[NHEADS];
#pragma unroll
            for (int h = 0; h < NHEADS; ++h)
                invgs[h] = 1.f / (stats[h] + stats[5 + h] + stats[10 + h] + stats[15 + h]);
            if (tid == 0) {
#pragma unroll
                for (int h = 0; h < NHEADS; ++h) {
                    float g = hp[h * 8 + 1], s5 = hp[h * 8 + 5];
                    A[h] += g * s5 * halo[h * 2];
                    B[h] += (1.f - g) * s5 * halo[h * 2 + 1];
                }
            }
            if (tid == SL - 1) {
#pragma unroll
                for (int h = 0; h < NHEADS; ++h) {
                    float g = hp[h * 8 + 1], s3 = hp[h * 8 + 3];
                    A[h] += g * s3 * halo[10 + h * 2];
                    B[h] += (1.f - g) * s3 * halo[10 + h * 2 + 1];
                }
            }
#pragma unroll
            for (int h = 0; h < NHEADS; ++h)
                wt[h] = __powf(fmaxf(fmaf(A[h], invgs[h], B[h]), 0.f), hp[h * 8 + 2]);
            RW4wr[tid] = make_float4(wt[0], wt[1], wt[2], wt[3]);
            wwwr[tid] = wt[4];
#pragma unroll
            for (int o = 16; o > 0; o >>= 1)
#pragma unroll
                for (int h = 0; h < NHEADS; ++h)
                    wt[h] += __shfl_xor_sync(0xffffffffu, wt[h], o);
            if (lane == 0)
#pragma unroll
                for (int h = 0; h < NHEADS; ++h) redb[wrp * 5 + h] = wt[h];
        }
        __syncthreads();  // S7

        // ---- ssum fold/send + GH pre-work (invW-independent a,u) ----
        if (tid < NHEADS) {
            float acc = redb[tid] + redb[5 + tid] + redb[10 + tid] + redb[15 + tid];
            ssum[r * 5 + tid] = acc;
#pragma unroll
            for (int c = 0; c < CSZ; ++c)
                if (c != (int)r) st_remote(pb[c] + (OFF_SSUM + (int)r * 5 + tid) * 4, acc);
        }
        {
            const int hp2 = tid >> 8;           // head pair 0:{0,1} 1:{2,3}
            const int q   = tid & 255;
            const int m   = q & 63;
            const int ng  = q >> 6;             // 4 slot groups of 32
            const float evr = evec[m], avr = avec[m];
            const float2* RW2 = reinterpret_cast<const float2*>(RWwr);
            float a0 = 0.f, a1 = 0.f, u0 = 0.f, u1 = 0.f;
            const int n0 = ng * 32;
#pragma unroll
            for (int n = n0; n < n0 + 32; ++n) {
                float wv = wwwr[n];
                float mv = Mem[n * MEMP + m];
                float un = wv * (avr - mv * evr);
                float2 rv = RW2[n * 2 + hp2];
                a0 = fmaf(mv, rv.x, a0); a1 = fmaf(mv, rv.y, a1);
                u0 = fmaf(un, rv.x, u0); u1 = fmaf(un, rv.y, u1);
            }
            const int h0 = hp2 * 2;
            buf[((h0 + 0) * 4 + ng) * 64 + m] = a0;
            buf[((h0 + 1) * 4 + ng) * 64 + m] = a1;
            buf[1024 + ((h0 + 0) * 4 + ng) * 64 + m] = u0;
            buf[1024 + ((h0 + 1) * 4 + ng) * 64 + m] = u1;
        }
        __syncthreads();  // S10
        if (tid < 256) {
            const int head = tid >> 6, m = tid & 63;
            float a = 0.f, u = 0.f;
#pragma unroll
            for (int ng = 0; ng < 4; ++ng) {
                a += buf[(head * 4 + ng) * 64 + m];
                u += buf[1024 + (head * 4 + ng) * 64 + m];
            }
            unsigned long long pk = pack2(a, u);
            rp2[r * 256 + tid] = pk;
#pragma unroll
            for (int c = 0; c < CSZ; ++c)
                if (c != (int)r)
                    st_remote64(pb[c] + (OFF_PX + ((int)r * 256 + tid) * 2) * 4, pk);
        }
        CLUSTER_SYNC();    // CS_m : ssum + (a,u) partials all present

        // ---- post: rvec fold (tid<256) || Mem update (tid>=256) ----
        {
            const float invW = 1.f / (ssum[4] + ssum[9] + ssum[14] + ssum[19] + 1e-8f);
            if (tid < 256) {
                const int head = tid >> 6;
                float sa = 0.f, su = 0.f;
#pragma unroll
                for (int c = 0; c < CSZ; ++c) {
                    unsigned long long pk = rp2[c * 256 + tid];
                    sa += __uint_as_float((unsigned int)pk);
                    su += __uint_as_float((unsigned int)(pk >> 32));
                }
                float sh = ssum[head] + ssum[5 + head] + ssum[10 + head] + ssum[15 + head];
                rvec[tid] = (sa + invW * su) / (sh + 1e-8f);
            } else {
                const int q = tid - 256;
                const int m = q & 63, ng = q >> 6;
                const float evr = evec[m], avr = avec[m];
                const int n0 = ng * 32;
#pragma unroll
                for (int n = n0; n < n0 + 32; ++n) {
                    float* mp = Mem + n * MEMP + m;
                    float mv = *mp;
                    *mp = mv + invW * (wwwr[n] * (avr - mv * evr));
                }
                if (q < NHEADS)
                    pinv[q] = 1.f / (ssum[q] + ssum[5 + q] + ssum[10 + q] + ssum[15 + q] + 1e-8f);
            }
        }
        __syncthreads();  // S11
    }
}

extern "C" void kernel_launch(void* const* d_in, const int* in_sizes, int n_in,
                              void* d_out, int out_size) {
    const float* x  = (const float*)d_in[0];
    const float* Wc = (const float*)d_in[1];
    const float* bc = (const float*)d_in[2];
    const float* hk = (const float*)d_in[3];
    const float* hb = (const float*)d_in[4];
    float* out = (float*)d_out;

    const size_t smem = SMEM_FLOATS * sizeof(float);
    cudaFuncSetAttribute(ntm_kernel, cudaFuncAttributeMaxDynamicSharedMemorySize, (int)smem);
    ntm_kernel<<<BATCH * CSZ, NT, smem>>>(x, Wc, bc, hk, hb, out);
}

// round 11
// speedup vs baseline: 1.8558x; 1.8558x over previous
#include <cuda_runtime.h>
#include <cstdint>
#include <math.h>

#define BATCH   32
#define TT      32
#define DIN     128
#define CSZ     4
#define SL      128
#define CTRLD   256
#define NHEADS  5
#define NT      512
#define MEMP    65

// ---- SMEM layout (float offsets) ----
#define OFF_MEM    0        // 8320
#define OFF_PX     8320     // 1920 : instr partials [cta][480]; rpart reuse
#define OFF_EXG    10240    // 650
#define OFF_HALO   10890    // 20 : L{ex,wp}x5, R{ex,wp}x5
#define OFF_STATS  10910    // 20
#define OFF_SSUM   10930    // 20
#define OFF_REDB   10950    // 80
#define OFF_KRED   11030    // 10
#define OFF_HP     11040    // 40
#define OFF_PINV   11080    // 8
#define OFF_RWA    11088    // 512
#define OFF_RWB    11600    // 512
#define OFF_WWA    12112    // 128
#define OFF_WWB    12240    // 128
#define OFF_RVEC   12368    // 256
#define OFF_H64    12624    // 64
#define OFF_KV     12688    // 320
#define OFF_EV     13008    // 64
#define OFF_AV     13072    // 64
#define OFF_HBS    13136    // 480
#define OFF_BUF    13616    // 2048
#define OFF_XP     15664    // 2048 : XP[t][64] = x_t @ Wc_x + bc
#define OFF_SWC    17712    // 8192 : mm1 r-rows 0..127 cache
#define OFF_SHK    25904    // 30720 : mm2 full cache, k-major stride 480
#define SMEM_FLOATS 56624   // 226496 bytes

__device__ __forceinline__ float sigmoidf_(float v) { return 1.f / (1.f + __expf(-v)); }
__device__ __forceinline__ float softplusf_(float v) { return v > 20.f ? v : log1pf(__expf(v)); }

__device__ __forceinline__ uint32_t smem_u32(const void* p) {
    uint32_t a;
    asm("{ .reg .u64 t; cvta.to.shared.u64 t, %1; cvt.u32.u64 %0, t; }" : "=r"(a) : "l"(p));
    return a;
}
__device__ __forceinline__ uint32_t mapa_u32(uint32_t a, uint32_t rank) {
    uint32_t r;
    asm("mapa.shared::cluster.u32 %0, %1, %2;" : "=r"(r) : "r"(a), "r"(rank));
    return r;
}
__device__ __forceinline__ void st_remote(uint32_t a, float v) {
    asm volatile("st.shared::cluster.f32 [%0], %1;" :: "r"(a), "f"(v) : "memory");
}
__device__ __forceinline__ void st_remote64(uint32_t a, unsigned long long v) {
    asm volatile("st.shared::cluster.u64 [%0], %1;" :: "r"(a), "l"(v) : "memory");
}
__device__ __forceinline__ uint32_t ctarank() {
    uint32_t r; asm("mov.u32 %0, %%cluster_ctarank;" : "=r"(r)); return r;
}
#define CLUSTER_ARRIVE() asm volatile("barrier.cluster.arrive.aligned;" ::: "memory")
#define CLUSTER_WAIT()   asm volatile("barrier.cluster.wait.aligned;" ::: "memory")
#define CLUSTER_SYNC() do { CLUSTER_ARRIVE(); CLUSTER_WAIT(); } while (0)

__device__ __forceinline__ unsigned long long pack2(float a, float b) {
    return (unsigned long long)__float_as_uint(a) |
           ((unsigned long long)__float_as_uint(b) << 32);
}

__global__ __launch_bounds__(NT, 1) __cluster_dims__(CSZ, 1, 1)
void ntm_kernel(const float* __restrict__ x, const float* __restrict__ Wc,
                const float* __restrict__ bc, const float* __restrict__ hk,
                const float* __restrict__ hb, float* __restrict__ out)
{
    extern __shared__ float sm[];
    float* Mem   = sm + OFF_MEM;
    float* px    = sm + OFF_PX;
    float* rpart = sm + OFF_PX;
    float* exg   = sm + OFF_EXG;
    float* halo  = sm + OFF_HALO;
    float* stats = sm + OFF_STATS;
    float* ssum  = sm + OFF_SSUM;
    float* redb  = sm + OFF_REDB;
    float* kred  = sm + OFF_KRED;
    float* hp    = sm + OFF_HP;
    float* pinv  = sm + OFF_PINV;
    float* rvec  = sm + OFF_RVEC;
    float* h64   = sm + OFF_H64;
    float* kvec  = sm + OFF_KV;
    float4* KV4  = reinterpret_cast<float4*>(kvec);
    float* evec  = sm + OFF_EV;
    float* avec  = sm + OFF_AV;
    float* hbs   = sm + OFF_HBS;
    float* buf   = sm + OFF_BUF;
    float* XP    = sm + OFF_XP;
    float4* XP4  = reinterpret_cast<float4*>(XP);
    float4* SWC4 = reinterpret_cast<float4*>(sm + OFF_SWC);
    float* SHK   = sm + OFF_SHK;

    const int tid  = threadIdx.x;
    const int wrp  = tid >> 5;
    const int lane = tid & 31;
    const int b    = blockIdx.x >> 2;
    const uint32_t r = ctarank();
    const uint32_t left  = (r + 3) & 3;
    const uint32_t right = (r + 1) & 3;

    const uint32_t sbase = smem_u32(sm);
    uint32_t pb[CSZ];
#pragma unroll
    for (int c = 0; c < CSZ; ++c) pb[c] = mapa_u32(sbase, c);

    // ---- init state ----
    for (int i = tid; i < SL * MEMP; i += NT) Mem[i] = 0.f;
    for (int i = tid; i < 512; i += NT) (sm + OFF_RWA)[i] = 0.f;
    if (tid < SL)  (sm + OFF_WWA)[tid] = 0.f;
    if (tid < 256) rvec[tid] = 0.f;
    if (tid < 8)   pinv[tid] = 1.f;
    if (tid < 478) hbs[tid] = hb[tid];
    {
        const float4* W4 = reinterpret_cast<const float4*>(Wc);
        // mm1 r-rows 0..127 cache (global rows 128..255), [wrp][k]
        for (int i = tid; i < 16 * 128; i += NT) {
            int w = i >> 7, k = i & 127;
            SWC4[i] = W4[(128 + k) * 64 + (int)r * 16 + w];
        }
        // mm2 full 64-row cache
        for (int kk = 0; kk < 64; ++kk)
            if (tid < 478)
                SHK[kk * 480 + tid] = hk[((int)r * 64 + kk) * 478 + tid];
        // XP[t][c] = x_t @ Wc_x (+ bc), per CTA column chunk
        {
            const int tt = tid >> 4, cg = tid & 15;
            const float* xr = x + (b * TT + tt) * DIN;
            float4 acc = make_float4(0.f, 0.f, 0.f, 0.f);
            const float4* Wx = W4 + (int)r * 16 + cg;
#pragma unroll 8
            for (int k = 0; k < 128; ++k) {
                float xv = xr[k];
                float4 w = Wx[k * 64];
                acc.x = fmaf(xv, w.x, acc.x); acc.y = fmaf(xv, w.y, acc.y);
                acc.z = fmaf(xv, w.z, acc.z); acc.w = fmaf(xv, w.w, acc.w);
            }
            float4 b4 = reinterpret_cast<const float4*>(bc)[(int)r * 16 + cg];
            acc.x += b4.x; acc.y += b4.y; acc.z += b4.z; acc.w += b4.w;
            XP4[tt * 16 + cg] = acc;
        }
    }
    __syncthreads();
    CLUSTER_SYNC();

    for (int t = 0; t < TT; ++t) {
        const int par = t & 1;
        float* RWrd = sm + (par ? OFF_RWB : OFF_RWA);
        float* RWwr = sm + (par ? OFF_RWA : OFF_RWB);
        float4* RW4rd = reinterpret_cast<float4*>(RWrd);
        float4* RW4wr = reinterpret_cast<float4*>(RWwr);
        float* wwrd = sm + (par ? OFF_WWB : OFF_WWA);
        float* wwwr = sm + (par ? OFF_WWA : OFF_WWB);

        // ---- B: mm1 r-part only (XP holds x-part + bias) ----
        {
            float a0 = 0.f, a1 = 0.f, a2 = 0.f, a3 = 0.f;
            const float4* cw = SWC4 + wrp * 128;
#pragma unroll
            for (int i = 0; i < 4; ++i) {               // cached k=0..127
                int k = lane + 32 * i;
                float c = rvec[k];
                float4 w = cw[k];
                a0 = fmaf(c, w.x, a0); a1 = fmaf(c, w.y, a1);
                a2 = fmaf(c, w.z, a2); a3 = fmaf(c, w.w, a3);
            }
            const float4* W4s = reinterpret_cast<const float4*>(Wc)
                                + 256 * 64 + (int)r * 16 + wrp;
#pragma unroll
            for (int i = 0; i < 4; ++i) {               // streamed k=128..255
                int k = lane + 32 * i;
                float c = rvec[128 + k];
                float4 w = W4s[k * 64];
                a0 = fmaf(c, w.x, a0); a1 = fmaf(c, w.y, a1);
                a2 = fmaf(c, w.z, a2); a3 = fmaf(c, w.w, a3);
            }
#pragma unroll
            for (int o = 16; o > 0; o >>= 1) {
                a0 += __shfl_xor_sync(0xffffffffu, a0, o);
                a1 += __shfl_xor_sync(0xffffffffu, a1, o);
                a2 += __shfl_xor_sync(0xffffffffu, a2, o);
                a3 += __shfl_xor_sync(0xffffffffu, a3, o);
            }
            if (lane < 4) {
                float av = (lane == 0) ? a0 : (lane == 1) ? a1 : (lane == 2) ? a2 : a3;
                float hv = tanhf(av + XP[t * 64 + 4 * wrp + lane]);
                h64[4 * wrp + lane] = hv;
                if (t == TT - 1) out[b * CTRLD + (int)r * 64 + 4 * wrp + lane] = hv;
            }
        }
        if (t == TT - 1) break;   // outs[-1] only needs h; skip final addressing pass
        __syncthreads();  // S1

        // ---- C: mm2 single pass, full SMEM ----
        if (wrp < 15) {
            float v = 0.f;
#pragma unroll 16
            for (int k = 0; k < 64; ++k)
                v = fmaf(h64[k], SHK[k * 480 + tid], v);
            if (tid < 478) px[r * 480 + tid] = v;
            float vo = __shfl_down_sync(0xffffffffu, v, 1);
            if (!(tid & 1) && tid < 477) {
                unsigned long long pk = pack2(v, vo);
#pragma unroll
                for (int c = 0; c < CSZ; ++c)
                    if (c != (int)r)
                        st_remote64(pb[c] + (OFF_PX + (int)r * 480 + tid) * 4, pk);
            }
        }
        CLUSTER_ARRIVE();  // CS2 arrive

        // ---- CS2 gap: Mem norms (Mem stable since GH) ----
        const int s  = tid >> 2;
        const int pq = tid & 3;
        float mn_reg;
        {
            float nn = 0.f;
            const float* mr = Mem + s * MEMP + pq * 16;
#pragma unroll
            for (int j = 0; j < 16; ++j) nn = fmaf(mr[j], mr[j], nn);
            nn += __shfl_xor_sync(0xffffffffu, nn, 1);
            nn += __shfl_xor_sync(0xffffffffu, nn, 2);
            mn_reg = sqrtf(nn);
        }
        CLUSTER_WAIT();    // CS2 wait

        // ---- D: parse (fold partials) ----
        if (tid < 320) {
            int h = tid >> 6, m = tid & 63;
            int idx = (h < 4 ? h * 70 : 280) + m;
            float v = px[idx] + px[480 + idx] + px[960 + idx] + px[1440 + idx] + hbs[idx];
            kvec[tid] = v;
            float sq = v * v;
#pragma unroll
            for (int o = 16; o > 0; o >>= 1) sq += __shfl_xor_sync(0xffffffffu, sq, o);
            if (lane == 0) kred[wrp] = sq;
        } else if (tid < 384) {
            int idx = 350 + (tid - 320);
            evec[tid - 320] = px[idx] + px[480 + idx] + px[960 + idx] + px[1440 + idx] + hbs[idx];
        } else if (tid < 448) {
            int idx = 414 + (tid - 384);
            avec[tid - 384] = px[idx] + px[480 + idx] + px[960 + idx] + px[1440 + idx] + hbs[idx];
        } else if (tid < 448 + NHEADS) {
            int h = tid - 448;
            int bidx = (h < 4 ? h * 70 : 280);
            float sv[6];
#pragma unroll
            for (int j = 0; j < 6; ++j) {
                int idx = bidx + 64 + j;
                sv[j] = px[idx] + px[480 + idx] + px[960 + idx] + px[1440 + idx] + hbs[idx];
            }
            hp[h * 8 + 0] = __expf(sv[0]);
            hp[h * 8 + 1] = sigmoidf_(sv[1]);
            float s0 = sv[2], s1 = sv[3], s2 = sv[4];
            float mx = fmaxf(s0, fmaxf(s1, s2));
            float e0 = __expf(s0 - mx), e1 = __expf(s1 - mx), e2 = __expf(s2 - mx);
            float inv = 1.f / (e0 + e1 + e2);
            hp[h * 8 + 3] = e0 * inv; hp[h * 8 + 4] = e1 * inv; hp[h * 8 + 5] = e2 * inv;
            hp[h * 8 + 2] = softplusf_(sv[5]) + 1.f;
        }
        __syncthreads();  // S3

        // ---- E: sim + exp (nn precomputed) ----
        float ex[NHEADS];
        {
            float d[NHEADS] = {0.f, 0.f, 0.f, 0.f, 0.f};
            const float* mr = Mem + s * MEMP + pq * 16;
#pragma unroll
            for (int j = 0; j < 4; ++j) {
                float m0 = mr[4 * j], m1 = mr[4 * j + 1], m2 = mr[4 * j + 2], m3 = mr[4 * j + 3];
#pragma unroll
                for (int h = 0; h < NHEADS; ++h) {
                    float4 kq = KV4[h * 16 + pq * 4 + j];
                    d[h] = fmaf(m0, kq.x, d[h]); d[h] = fmaf(m1, kq.y, d[h]);
                    d[h] = fmaf(m2, kq.z, d[h]); d[h] = fmaf(m3, kq.w, d[h]);
                }
            }
#pragma unroll
            for (int o = 1; o <= 2; o <<= 1)
#pragma unroll
                for (int h = 0; h < NHEADS; ++h) d[h] += __shfl_xor_sync(0xffffffffu, d[h], o);
#pragma unroll
            for (int h = 0; h < NHEADS; ++h) {
                float kn = sqrtf(kred[2 * h] + kred[2 * h + 1]);
                float z = hp[h * 8 + 0] * (d[h] / (kn * mn_reg + 1e-8f));
                ex[h] = __expf(z);
            }
        }
        if (pq == 0) {
#pragma unroll
            for (int h = 0; h < NHEADS; ++h) exg[h * 130 + s + 1] = ex[h];
        }
        if (tid == 0) {
            float4 wp4 = RW4rd[0];
            float wpv[5] = {wp4.x * pinv[0], wp4.y * pinv[1], wp4.z * pinv[2],
                            wp4.w * pinv[3], wwrd[0] * pinv[4]};
#pragma unroll
            for (int h = 0; h < NHEADS; ++h)
                st_remote64(pb[left] + (OFF_HALO + 10 + h * 2) * 4, pack2(ex[h], wpv[h]));
        }
        if (tid == (SL - 1) * 4) {
            float4 wp4 = RW4rd[SL - 1];
            float wpv[5] = {wp4.x * pinv[0], wp4.y * pinv[1], wp4.z * pinv[2],
                            wp4.w * pinv[3], wwrd[SL - 1] * pinv[4]};
#pragma unroll
            for (int h = 0; h < NHEADS; ++h)
                st_remote64(pb[right] + (OFF_HALO + h * 2) * 4, pack2(ex[h], wpv[h]));
        }
        {
            float tmp[NHEADS];
#pragma unroll
            for (int h = 0; h < NHEADS; ++h) tmp[h] = (pq == 0) ? ex[h] : 0.f;
#pragma unroll
            for (int o = 16; o > 0; o >>= 1)
#pragma unroll
                for (int h = 0; h < NHEADS; ++h)
                    tmp[h] += __shfl_xor_sync(0xffffffffu, tmp[h], o);
            if (lane == 0)
#pragma unroll
                for (int h = 0; h < NHEADS; ++h) redb[wrp * 5 + h] = tmp[h];
        }
        __syncthreads();  // S4
        if (tid < NHEADS) {
            float acc = 0.f;
#pragma unroll
            for (int w = 0; w < 16; ++w) acc += redb[w * 5 + tid];
            stats[r * 5 + tid] = acc;
#pragma unroll
            for (int c = 0; c < CSZ; ++c)
                if (c != (int)r) st_remote(pb[c] + (OFF_STATS + (int)r * 5 + tid) * 4, acc);
        }
        CLUSTER_ARRIVE();  // CS3 arrive

        // ---- CS3 gap: preload F's local wp values (raw) ----
        float wpcR[5], wpmR[5], wppR[5];
        if (tid < SL) {
            float4 wc4 = RW4rd[tid];
            wpcR[0] = wc4.x; wpcR[1] = wc4.y; wpcR[2] = wc4.z; wpcR[3] = wc4.w;
            wpcR[4] = wwrd[tid];
            int im = (tid > 0) ? tid - 1 : 0;
            int ip = (tid < SL - 1) ? tid + 1 : SL - 1;
            float4 w4m = RW4rd[im];
            wpmR[0] = w4m.x; wpmR[1] = w4m.y; wpmR[2] = w4m.z; wpmR[3] = w4m.w;
            wpmR[4] = wwrd[im];
            float4 w4p = RW4rd[ip];
            wppR[0] = w4p.x; wppR[1] = w4p.y; wppR[2] = w4p.z; wppR[3] = w4p.w;
            wppR[4] = wwrd[ip];
        }
        CLUSTER_WAIT();    // CS3 wait

        // ---- F fused: wg + shift + sharpen (halo-ex FIXED) ----
        if (tid < SL) {
            float wt[NHEADS];
            float invgs[NHEADS];
#pragma unroll
            for (int h = 0; h < NHEADS; ++h)
                invgs[h] = 1.f / (stats[h] + stats[5 + h] + stats[10 + h] + stats[15 + h]);
#pragma unroll
            for (int h = 0; h < NHEADS; ++h) {
                float pv = pinv[h];
                float wpm = (tid > 0)      ? wpmR[h] * pv : halo[h * 2 + 1];
                float wpc = wpcR[h] * pv;
                float wpp = (tid < SL - 1) ? wppR[h] * pv : halo[10 + h * 2 + 1];
                float g = hp[h * 8 + 1];
                float exm  = (tid > 0)      ? exg[h * 130 + tid]     : halo[h * 2];
                float exc  = exg[h * 130 + tid + 1];
                float exp_ = (tid < SL - 1) ? exg[h * 130 + tid + 2] : halo[10 + h * 2];
                float wgm = g * (exm * invgs[h]) + (1.f - g) * wpm;
                float wgc = g * (exc * invgs[h]) + (1.f - g) * wpc;
                float wgp = g * (exp_ * invgs[h]) + (1.f - g) * wpp;
                float wsh = hp[h * 8 + 3] * wgp + hp[h * 8 + 4] * wgc + hp[h * 8 + 5] * wgm;
                wt[h] = __powf(fmaxf(wsh, 0.f), hp[h * 8 + 2]);
            }
            RW4wr[tid] = make_float4(wt[0], wt[1], wt[2], wt[3]);
            wwwr[tid] = wt[4];
#pragma unroll
            for (int o = 16; o > 0; o >>= 1)
#pragma unroll
                for (int h = 0; h < NHEADS; ++h)
                    wt[h] += __shfl_xor_sync(0xffffffffu, wt[h], o);
            if (lane == 0)
#pragma unroll
                for (int h = 0; h < NHEADS; ++h) redb[wrp * 5 + h] = wt[h];
        }
        __syncthreads();  // S7
        if (tid < NHEADS) {
            float acc = redb[tid] + redb[5 + tid] + redb[10 + tid] + redb[15 + tid];
            ssum[r * 5 + tid] = acc;
#pragma unroll
            for (int c = 0; c < CSZ; ++c)
                if (c != (int)r) st_remote(pb[c] + (OFF_SSUM + (int)r * 5 + tid) * 4, acc);
        }
        CLUSTER_ARRIVE();  // CS5 arrive

        // ---- CS5 gap: GH pre-work (invW-independent by linearity) ----
        const int m  = tid & 63;
        const int ng = tid >> 6;
        const int n0 = ng * 16;
        const float evr = evec[m], avr = avec[m];
        float a0 = 0.f, a1 = 0.f, a2 = 0.f, a3 = 0.f;
        float u0 = 0.f, u1 = 0.f, u2 = 0.f, u3 = 0.f;
#pragma unroll
        for (int n = n0; n < n0 + 16; ++n) {
            float wv = wwwr[n];
            float mv = Mem[n * MEMP + m];
            float un = wv * (avr - mv * evr);
            float4 rv = RW4wr[n];
            a0 = fmaf(mv, rv.x, a0); a1 = fmaf(mv, rv.y, a1);
            a2 = fmaf(mv, rv.z, a2); a3 = fmaf(mv, rv.w, a3);
            u0 = fmaf(un, rv.x, u0); u1 = fmaf(un, rv.y, u1);
            u2 = fmaf(un, rv.z, u2); u3 = fmaf(un, rv.w, u3);
        }
        CLUSTER_WAIT();    // CS5 wait

        // ---- GH finish: fold invW, update Mem, emit read partials ----
        {
            if (tid < NHEADS)
                pinv[tid] = 1.f / (ssum[tid] + ssum[5 + tid] + ssum[10 + tid] + ssum[15 + tid] + 1e-8f);
            const float invW = 1.f / (ssum[4] + ssum[9] + ssum[14] + ssum[19] + 1e-8f);
#pragma unroll
            for (int n = n0; n < n0 + 16; ++n) {
                float* mp = Mem + n * MEMP + m;
                float mv = *mp;
                float wv = wwwr[n];
                *mp = mv + invW * (wv * (avr - mv * evr));
            }
            buf[ng * 256 + 0 * 64 + m] = fmaf(invW, u0, a0);
            buf[ng * 256 + 1 * 64 + m] = fmaf(invW, u1, a1);
            buf[ng * 256 + 2 * 64 + m] = fmaf(invW, u2, a2);
            buf[ng * 256 + 3 * 64 + m] = fmaf(invW, u3, a3);
        }
        __syncthreads();  // S10
        if (tid < 128) {
            float v0 = 0.f, v1 = 0.f;
#pragma unroll
            for (int g2 = 0; g2 < 8; ++g2) {
                v0 += buf[g2 * 256 + 2 * tid];
                v1 += buf[g2 * 256 + 2 * tid + 1];
            }
            rpart[r * 256 + 2 * tid]     = v0;
            rpart[r * 256 + 2 * tid + 1] = v1;
            unsigned long long pk = pack2(v0, v1);
#pragma unroll
            for (int c = 0; c < CSZ; ++c)
                if (c != (int)r)
                    st_remote64(pb[c] + (OFF_PX + (int)r * 256 + 2 * tid) * 4, pk);
        }
        CLUSTER_SYNC();  // CS6
        if (tid < 256) {
            int h = tid >> 6;
            rvec[tid] = (rpart[tid] + rpart[256 + tid] + rpart[512 + tid] + rpart[768 + tid])
                        * pinv[h];
        }
        __syncthreads();  // S11
    }
}

extern "C" void kernel_launch(void* const* d_in, const int* in_sizes, int n_in,
                              void* d_out, int out_size) {
    const float* x  = (const float*)d_in[0];
    const float* Wc = (const float*)d_in[1];
    const float* bc = (const float*)d_in[2];
    const float* hk = (const float*)d_in[3];
    const float* hb = (const float*)d_in[4];
    float* out = (float*)d_out;

    const size_t smem = SMEM_FLOATS * sizeof(float);
    cudaFuncSetAttribute(ntm_kernel, cudaFuncAttributeMaxDynamicSharedMemorySize, (int)smem);
    ntm_kernel<<<BATCH * CSZ, NT, smem>>>(x, Wc, bc, hk, hb, out);
}